// round 1
// baseline (speedup 1.0000x reference)
#include <cuda_runtime.h>
#include <math.h>

#define EMB   300
#define EMB2  600
#define NG    4096
#define NL    5
#define MAXN  100000
#define MAXE  400000
#define BN_EPS 1e-5f
#define INV_TEMP 25.0f

// ---------------- scratch (device globals; no allocation allowed) -----------
__device__ float g_h   [(size_t)MAXN * EMB];
__device__ float g_agg [(size_t)MAXN * EMB];
__device__ float g_h2  [(size_t)MAXN * EMB2];
__device__ float g_stats[2 * EMB];
__device__ float g_feat0[(size_t)NG * EMB];
__device__ float g_feat1[(size_t)NG * EMB];
__device__ float g_cnt [NG];
__device__ float g_f1t [(size_t)EMB * NG];

// ---------------- small utility kernels -------------------------------------
__global__ void zero_kernel(float* p, int n) {
    int i = blockIdx.x * blockDim.x + threadIdx.x;
    if (i < n) p[i] = 0.f;
}

// h[i,c] = atom_emb1[x[i,0],c] + atom_emb2[x[i,1],c]
__global__ void init_h_kernel(const int* __restrict__ x,
                              const float* __restrict__ ae1,
                              const float* __restrict__ ae2,
                              float* __restrict__ h, int n) {
    int idx = blockIdx.x * blockDim.x + threadIdx.x;
    if (idx >= n * EMB) return;
    int i = idx / EMB, c = idx - i * EMB;
    h[idx] = ae1[x[2 * i] * EMB + c] + ae2[x[2 * i + 1] * EMB + c];
}

// agg[i,c] = h[i,c] + self_emb[c]   (self-loop edge_attr = [4,0])
__global__ void agg_init_kernel(const float* __restrict__ h,
                                const float* __restrict__ e1l,
                                const float* __restrict__ e2l,
                                float* __restrict__ agg, int n) {
    int idx = blockIdx.x * blockDim.x + threadIdx.x;
    if (idx >= n * EMB) return;
    int c = idx % EMB;
    agg[idx] = h[idx] + e1l[4 * EMB + c] + e2l[c];
}

// per edge e: agg[dst[e]] += h[src[e]] + edge_emb1[l][ea0] + edge_emb2[l][ea1]
__global__ void scatter_kernel(const float* __restrict__ h,
                               const int* __restrict__ ei,
                               const int* __restrict__ ea,
                               const float* __restrict__ e1l,
                               const float* __restrict__ e2l,
                               float* __restrict__ agg, int E) {
    int gw   = (blockIdx.x * blockDim.x + threadIdx.x) >> 5;
    int lane = threadIdx.x & 31;
    if (gw >= E) return;
    int s  = ei[gw];
    int d  = ei[E + gw];
    int a0 = ea[2 * gw];
    int a1 = ea[2 * gw + 1];
    const float* hs = h   + (size_t)s * EMB;
    const float* t1 = e1l + (size_t)a0 * EMB;
    const float* t2 = e2l + (size_t)a1 * EMB;
    float* ad = agg + (size_t)d * EMB;
    for (int c = lane; c < EMB; c += 32)
        atomicAdd(ad + c, hs[c] + t1[c] + t2[c]);
}

// ---------------- tiled SGEMM: C = act(alpha*(A@B) + bias) ------------------
// A [M,K] row-major, B [K,N] row-major, C [M,N]. 256 threads, 128x64 tile,
// BK=16, each thread 8x4 in registers, float4 smem reads.
#define TBM 128
#define TBN 64
#define TBK 16
__global__ __launch_bounds__(256)
void sgemm_kernel(const float* __restrict__ A, const float* __restrict__ B,
                  const float* __restrict__ bias, float* __restrict__ C,
                  int M, int N, int K, float alpha, int do_relu) {
    __shared__ float As[TBK][TBM];
    __shared__ float Bs[TBK][TBN];
    int tid = threadIdx.x;
    int tx = tid & 15, ty = tid >> 4;
    int m0 = blockIdx.y * TBM;
    int n0 = blockIdx.x * TBN;
    float acc[8][4];
#pragma unroll
    for (int r = 0; r < 8; r++)
#pragma unroll
        for (int c = 0; c < 4; c++) acc[r][c] = 0.f;

    for (int kt = 0; kt < K; kt += TBK) {
#pragma unroll
        for (int i = 0; i < 8; i++) {           // 2048 A elems
            int e = tid + i * 256;
            int r = e >> 4, c = e & 15;
            int gm = m0 + r, gk = kt + c;
            As[c][r] = (gm < M && gk < K) ? A[(size_t)gm * K + gk] : 0.f;
        }
#pragma unroll
        for (int i = 0; i < 4; i++) {           // 1024 B elems
            int e = tid + i * 256;
            int r = e >> 6, c = e & 63;
            int gk = kt + r, gn = n0 + c;
            Bs[r][c] = (gk < K && gn < N) ? B[(size_t)gk * N + gn] : 0.f;
        }
        __syncthreads();
#pragma unroll
        for (int k = 0; k < TBK; k++) {
            float4 a0 = *(const float4*)&As[k][ty * 8];
            float4 a1 = *(const float4*)&As[k][ty * 8 + 4];
            float4 b0 = *(const float4*)&Bs[k][tx * 4];
            float a[8] = {a0.x, a0.y, a0.z, a0.w, a1.x, a1.y, a1.z, a1.w};
            float b[4] = {b0.x, b0.y, b0.z, b0.w};
#pragma unroll
            for (int r = 0; r < 8; r++)
#pragma unroll
                for (int c = 0; c < 4; c++)
                    acc[r][c] += a[r] * b[c];
        }
        __syncthreads();
    }
#pragma unroll
    for (int r = 0; r < 8; r++) {
        int gm = m0 + ty * 8 + r;
        if (gm >= M) continue;
#pragma unroll
        for (int c = 0; c < 4; c++) {
            int gn = n0 + tx * 4 + c;
            if (gn >= N) continue;
            float v = acc[r][c] * alpha;
            if (bias) v += bias[gn];
            if (do_relu) v = fmaxf(v, 0.f);
            C[(size_t)gm * N + gn] = v;
        }
    }
}

// ---------------- batchnorm ---------------------------------------------------
// partial column sums/sumsq -> atomic into g_stats
__global__ void bn_stats_kernel(const float* __restrict__ h, int n) {
    int t = threadIdx.x;
    if (t >= EMB) return;
    float s = 0.f, sq = 0.f;
    for (int r = blockIdx.x; r < n; r += gridDim.x) {
        float v = h[(size_t)r * EMB + t];
        s += v; sq += v * v;
    }
    atomicAdd(&g_stats[t], s);
    atomicAdd(&g_stats[EMB + t], sq);
}

__global__ void bn_apply_kernel(float* __restrict__ h,
                                const float* __restrict__ gamma,
                                const float* __restrict__ beta,
                                int n, int do_relu) {
    int idx = blockIdx.x * blockDim.x + threadIdx.x;
    if (idx >= n * EMB) return;
    int c = idx % EMB;
    float invn = 1.f / (float)n;
    float mean = g_stats[c] * invn;
    float var  = g_stats[EMB + c] * invn - mean * mean;
    float inv  = rsqrtf(var + BN_EPS);
    float v = (h[idx] - mean) * inv * gamma[c] + beta[c];
    if (do_relu) v = fmaxf(v, 0.f);
    h[idx] = v;
}

// ---------------- pooling + normalize ----------------------------------------
__global__ void pool_kernel(const float* __restrict__ p,
                            const int* __restrict__ batch,
                            float* __restrict__ feat, float* __restrict__ cnt,
                            int n) {
    int gw   = (blockIdx.x * blockDim.x + threadIdx.x) >> 5;
    int lane = threadIdx.x & 31;
    if (gw >= n) return;
    int b = batch[gw];
    if (lane == 0) atomicAdd(&cnt[b], 1.f);
    const float* pr = p + (size_t)gw * EMB;
    float* fr = feat + (size_t)b * EMB;
    for (int c = lane; c < EMB; c += 32)
        atomicAdd(fr + c, pr[c]);
}

__global__ void norm_feat_kernel(float* __restrict__ feat,
                                 const float* __restrict__ cnt) {
    __shared__ float red[16];
    int g = blockIdx.x, t = threadIdx.x;
    float c = fmaxf(cnt[g], 1.f);
    float v = 0.f;
    if (t < EMB) v = feat[(size_t)g * EMB + t] / c;
    float sq = v * v;
#pragma unroll
    for (int o = 16; o; o >>= 1) sq += __shfl_xor_sync(0xffffffffu, sq, o);
    if ((t & 31) == 0) red[t >> 5] = sq;
    __syncthreads();
    if (t < 32) {
        float s = (t < (int)(blockDim.x >> 5)) ? red[t] : 0.f;
#pragma unroll
        for (int o = 16; o; o >>= 1) s += __shfl_xor_sync(0xffffffffu, s, o);
        if (t == 0) red[0] = s;
    }
    __syncthreads();
    float nrm = fmaxf(sqrtf(red[0]), 1e-12f);
    if (t < EMB) feat[(size_t)g * EMB + t] = v / nrm;
}

// transpose [NG,EMB] -> [EMB,NG]
__global__ void transpose_kernel(const float* __restrict__ f,
                                 float* __restrict__ ft) {
    int idx = blockIdx.x * blockDim.x + threadIdx.x;
    if (idx >= NG * EMB) return;
    int g = idx / EMB, c = idx - g * EMB;
    ft[(size_t)c * NG + g] = f[idx];
}

// ---------------- driver ------------------------------------------------------
extern "C" void kernel_launch(void* const* d_in, const int* in_sizes, int n_in,
                              void* d_out, int out_size) {
    const int* x[2]  = {(const int*)d_in[0], (const int*)d_in[4]};
    const int* ei[2] = {(const int*)d_in[1], (const int*)d_in[5]};
    const int* ea[2] = {(const int*)d_in[2], (const int*)d_in[6]};
    const int* bt[2] = {(const int*)d_in[3], (const int*)d_in[7]};
    const float* ae1 = (const float*)d_in[8];
    const float* ae2 = (const float*)d_in[9];
    const float* ee1 = (const float*)d_in[10];
    const float* ee2 = (const float*)d_in[11];
    const float* w1  = (const float*)d_in[12];
    const float* b1  = (const float*)d_in[13];
    const float* w2  = (const float*)d_in[14];
    const float* b2  = (const float*)d_in[15];
    const float* gam = (const float*)d_in[16];
    const float* bet = (const float*)d_in[17];
    const float* pw  = (const float*)d_in[18];
    const float* pb  = (const float*)d_in[19];

    int Nn[2] = {in_sizes[0] / 2, in_sizes[4] / 2};
    int Ee[2] = {in_sizes[1] / 2, in_sizes[5] / 2};

    float *h, *agg, *h2, *stats, *feat0, *feat1, *cnt, *f1t;
    cudaGetSymbolAddress((void**)&h,     g_h);
    cudaGetSymbolAddress((void**)&agg,   g_agg);
    cudaGetSymbolAddress((void**)&h2,    g_h2);
    cudaGetSymbolAddress((void**)&stats, g_stats);
    cudaGetSymbolAddress((void**)&feat0, g_feat0);
    cudaGetSymbolAddress((void**)&feat1, g_feat1);
    cudaGetSymbolAddress((void**)&cnt,   g_cnt);
    cudaGetSymbolAddress((void**)&f1t,   g_f1t);

    for (int br = 0; br < 2; br++) {
        int n = Nn[br], e = Ee[br];
        float* feat_b = br ? feat1 : feat0;
        int elemBlocks = (n * EMB + 255) / 256;

        init_h_kernel<<<elemBlocks, 256>>>(x[br], ae1, ae2, h, n);

        for (int l = 0; l < NL; l++) {
            const float* e1l = ee1 + (size_t)l * 6 * EMB;
            const float* e2l = ee2 + (size_t)l * 3 * EMB;

            agg_init_kernel<<<elemBlocks, 256>>>(h, e1l, e2l, agg, n);
            scatter_kernel<<<(e * 32 + 255) / 256, 256>>>(h, ei[br], ea[br],
                                                          e1l, e2l, agg, e);
            // h2 = relu(agg @ W1 + b1)   [n,300]x[300,600]
            sgemm_kernel<<<dim3((EMB2 + TBN - 1) / TBN, (n + TBM - 1) / TBM), 256>>>(
                agg, w1 + (size_t)l * EMB * EMB2, b1 + (size_t)l * EMB2,
                h2, n, EMB2, EMB, 1.f, 1);
            // h = h2 @ W2 + b2          [n,600]x[600,300]
            sgemm_kernel<<<dim3((EMB + TBN - 1) / TBN, (n + TBM - 1) / TBM), 256>>>(
                h2, w2 + (size_t)l * EMB2 * EMB, b2 + (size_t)l * EMB,
                h, n, EMB, EMB2, 1.f, 0);

            zero_kernel<<<(2 * EMB + 255) / 256, 256>>>(stats, 2 * EMB);
            bn_stats_kernel<<<512, 320>>>(h, n);
            bn_apply_kernel<<<elemBlocks, 256>>>(h, gam + (size_t)l * EMB,
                                                 bet + (size_t)l * EMB,
                                                 n, l != NL - 1);
        }
        // projector: agg = h @ proj_w + proj_b
        sgemm_kernel<<<dim3((EMB + TBN - 1) / TBN, (n + TBM - 1) / TBM), 256>>>(
            h, pw, pb, agg, n, EMB, EMB, 1.f, 0);

        zero_kernel<<<(NG * EMB + 255) / 256, 256>>>(feat_b, NG * EMB);
        zero_kernel<<<(NG + 255) / 256, 256>>>(cnt, NG);
        pool_kernel<<<(n * 32 + 255) / 256, 256>>>(agg, bt[br], feat_b, cnt, n);
        norm_feat_kernel<<<NG, 320>>>(feat_b, cnt);
    }

    // logits = f0 @ f1^T / TEMP
    transpose_kernel<<<(NG * EMB + 255) / 256, 256>>>(feat1, f1t);
    sgemm_kernel<<<dim3(NG / TBN, NG / TBM), 256>>>(
        feat0, f1t, nullptr, (float*)d_out, NG, NG, EMB, INV_TEMP, 0);
}

// round 2
// speedup vs baseline: 1.5102x; 1.5102x over previous
#include <cuda_runtime.h>
#include <math.h>

#define EMB   300
#define EMB2  600
#define NG    4096
#define NL    5
#define MAXN  100000
#define MAXE  400000
#define BN_EPS 1e-5f
#define INV_TEMP 25.0f

// ---------------- scratch (device globals; no allocation allowed) -----------
__device__ float g_h   [(size_t)MAXN * EMB];
__device__ float g_agg [(size_t)MAXN * EMB];
__device__ float g_h2  [(size_t)MAXN * EMB2];
__device__ float g_stats[2 * EMB];
__device__ float g_feat0[(size_t)NG * EMB];
__device__ float g_feat1[(size_t)NG * EMB];
__device__ float g_cnt [NG];
__device__ float g_f1t [(size_t)EMB * NG];
__device__ float g_etab[(size_t)NL * 18 * EMB];   // e1[a0]+e2[a1] per layer
__device__ int   g_off [MAXN + 1];
__device__ int   g_cur [MAXN];
__device__ int   g_bsum[256];
__device__ int   g_csr [MAXE];

// ---------------- small utility kernels -------------------------------------
__global__ void zero_f(float* p, int n) {
    int i = blockIdx.x * blockDim.x + threadIdx.x;
    if (i < n) p[i] = 0.f;
}
__global__ void zero_i(int* p, int n) {
    int i = blockIdx.x * blockDim.x + threadIdx.x;
    if (i < n) p[i] = 0;
}

// h[i,c] = atom_emb1[x[i,0],c] + atom_emb2[x[i,1],c]
__global__ void init_h_kernel(const int* __restrict__ x,
                              const float* __restrict__ ae1,
                              const float* __restrict__ ae2,
                              float* __restrict__ h, int n) {
    int idx = blockIdx.x * blockDim.x + threadIdx.x;
    if (idx >= n * EMB) return;
    int i = idx / EMB, c = idx - i * EMB;
    h[idx] = ae1[x[2 * i] * EMB + c] + ae2[x[2 * i + 1] * EMB + c];
}

// etab[l][a0*3+a1][c] = ee1[l][a0][c] + ee2[l][a1][c]
__global__ void etab_kernel(const float* __restrict__ ee1,
                            const float* __restrict__ ee2,
                            float* __restrict__ et) {
    int idx = blockIdx.x * blockDim.x + threadIdx.x;
    if (idx >= NL * 18 * EMB) return;
    int l = idx / (18 * EMB);
    int r = idx - l * 18 * EMB;
    int combo = r / EMB, c = r - combo * EMB;
    int a0 = combo / 3, a1 = combo - a0 * 3;
    et[idx] = ee1[(size_t)l * 6 * EMB + a0 * EMB + c] +
              ee2[(size_t)l * 3 * EMB + a1 * EMB + c];
}

// ---------------- CSR build ---------------------------------------------------
__global__ void count_deg_kernel(const int* __restrict__ ei, int* __restrict__ deg,
                                 int E) {
    int e = blockIdx.x * blockDim.x + threadIdx.x;
    if (e < E) atomicAdd(&deg[ei[E + e]], 1);
}

// block-level inclusive scan of deg -> off[i+1]; block totals -> bsum
__global__ void scan1_kernel(const int* __restrict__ deg, int* __restrict__ off,
                             int* __restrict__ bsum, int n) {
    __shared__ int s[1024];
    int t = threadIdx.x;
    int i = blockIdx.x * 1024 + t;
    int v = (i < n) ? deg[i] : 0;
    s[t] = v;
    __syncthreads();
    for (int o = 1; o < 1024; o <<= 1) {
        int add = (t >= o) ? s[t - o] : 0;
        __syncthreads();
        s[t] += add;
        __syncthreads();
    }
    if (i < n) off[i + 1] = s[t];
    if (t == 1023) bsum[blockIdx.x] = s[1023];
}

__global__ void scan2_kernel(int* bsum, int G) {
    if (threadIdx.x == 0 && blockIdx.x == 0) {
        int run = 0;
        for (int b = 0; b < G; b++) { int v = bsum[b]; bsum[b] = run; run += v; }
    }
}

__global__ void scan3_kernel(int* __restrict__ off, const int* __restrict__ bsum,
                             int n) {
    int i = blockIdx.x * 1024 + threadIdx.x;
    if (i < n) off[i + 1] += bsum[blockIdx.x];
    if (i == 0) off[0] = 0;
}

__global__ void copy_cur_kernel(const int* __restrict__ off, int* __restrict__ cur,
                                int n) {
    int i = blockIdx.x * blockDim.x + threadIdx.x;
    if (i < n) cur[i] = off[i];
}

// csr[pos] = src | (attr_combo << 20)
__global__ void fill_csr_kernel(const int* __restrict__ ei, const int* __restrict__ ea,
                                int* __restrict__ cur, int* __restrict__ csr, int E) {
    int e = blockIdx.x * blockDim.x + threadIdx.x;
    if (e >= E) return;
    int d = ei[E + e];
    int p = atomicAdd(&cur[d], 1);
    int a = ea[2 * e] * 3 + ea[2 * e + 1];
    csr[p] = ei[e] | (a << 20);
}

// ---------------- message aggregation (gather, no atomics) -------------------
// one warp per dst: agg[d] = h[d] + etab[12] + sum_{edges->d} (h[src]+etab[attr])
__global__ void gather_kernel(const float* __restrict__ h,
                              const int* __restrict__ off,
                              const int* __restrict__ csr,
                              const float* __restrict__ et,
                              float* __restrict__ agg, int n) {
    int w    = (blockIdx.x * blockDim.x + threadIdx.x) >> 5;
    int lane = threadIdx.x & 31;
    if (w >= n) return;
    int o0 = off[w], o1 = off[w + 1];
    const float* hd    = h + (size_t)w * EMB;
    const float* selft = et + 12 * EMB;   // combo (4,0) = self-loop
    float r[10];
#pragma unroll
    for (int j = 0; j < 10; j++) {
        int c = lane + 32 * j;
        r[j] = (c < EMB) ? hd[c] + selft[c] : 0.f;
    }
    for (int o = o0; o < o1; o++) {
        int pk = csr[o];
        const float* hs = h  + (size_t)(pk & 0xFFFFF) * EMB;
        const float* tt = et + (size_t)(pk >> 20) * EMB;
#pragma unroll
        for (int j = 0; j < 10; j++) {
            int c = lane + 32 * j;
            if (c < EMB) r[j] += hs[c] + tt[c];
        }
    }
    float* ad = agg + (size_t)w * EMB;
#pragma unroll
    for (int j = 0; j < 10; j++) {
        int c = lane + 32 * j;
        if (c < EMB) ad[c] = r[j];
    }
}

// ---------------- 3xTF32 tensor-core GEMM ------------------------------------
// C[M,N] = act(alpha * A[M,K] @ B[K,N] + bias). row-major A, B.
// Block 256 thr (8 warps), tile 128x64, BK=16, warp tile 32x32.
#define BM 128
#define BNT 64
#define BK 16

__device__ __forceinline__ unsigned f2tf32(float v) {
    unsigned r;
    asm("cvt.rna.tf32.f32 %0, %1;" : "=r"(r) : "f"(v));
    return r;
}
__device__ __forceinline__ void split_tf32(float v, unsigned& hi, unsigned& lo) {
    hi = f2tf32(v);
    lo = f2tf32(v - __uint_as_float(hi));
}
__device__ __forceinline__ void mma_tf32(float* c, const unsigned* a, const unsigned* b) {
    asm volatile(
        "mma.sync.aligned.m16n8k8.row.col.f32.tf32.tf32.f32 "
        "{%0,%1,%2,%3},{%4,%5,%6,%7},{%8,%9},{%0,%1,%2,%3};"
        : "+f"(c[0]), "+f"(c[1]), "+f"(c[2]), "+f"(c[3])
        : "r"(a[0]), "r"(a[1]), "r"(a[2]), "r"(a[3]), "r"(b[0]), "r"(b[1]));
}

__global__ __launch_bounds__(256)
void gemm_tf32_kernel(const float* __restrict__ A, const float* __restrict__ B,
                      const float* __restrict__ bias, float* __restrict__ C,
                      int M, int N, int K, float alpha, int do_relu) {
    __shared__ float As[BM][BK + 4];   // stride 20 words: conflict-free frag loads
    __shared__ float Bs[BK][BNT + 8];  // stride 72 words: conflict-free frag loads

    int tid  = threadIdx.x;
    int wid  = tid >> 5;
    int lane = tid & 31;
    int g    = lane >> 2;      // groupID 0..7
    int tig  = lane & 3;       // thread-in-group 0..3
    int wm   = (wid & 3) * 32; // warp m offset
    int wn   = (wid >> 2) * 32;// warp n offset
    int bm0  = blockIdx.y * BM;
    int bn0  = blockIdx.x * BNT;

    float acc[2][4][4];
#pragma unroll
    for (int mt = 0; mt < 2; mt++)
#pragma unroll
        for (int nt = 0; nt < 4; nt++)
#pragma unroll
            for (int q = 0; q < 4; q++) acc[mt][nt][q] = 0.f;

    int nk = (K + BK - 1) / BK;
    float areg[8], breg[4];

    // prefetch tile 0
#pragma unroll
    for (int i = 0; i < 8; i++) {
        int e = tid + i * 256, r = e >> 4, c = e & 15;
        int gm = bm0 + r, gk = c;
        areg[i] = (gm < M && gk < K) ? A[(size_t)gm * K + gk] : 0.f;
    }
#pragma unroll
    for (int i = 0; i < 4; i++) {
        int e = tid + i * 256, r = e >> 6, c = e & 63;
        int gk = r, gn = bn0 + c;
        breg[i] = (gk < K && gn < N) ? B[(size_t)gk * N + gn] : 0.f;
    }
#pragma unroll
    for (int i = 0; i < 8; i++) { int e = tid + i * 256; As[e >> 4][e & 15] = areg[i]; }
#pragma unroll
    for (int i = 0; i < 4; i++) { int e = tid + i * 256; Bs[e >> 6][e & 63] = breg[i]; }
    __syncthreads();

    for (int step = 0; step < nk; step++) {
        int ktn = (step + 1) * BK;
        if (step + 1 < nk) {
#pragma unroll
            for (int i = 0; i < 8; i++) {
                int e = tid + i * 256, r = e >> 4, c = e & 15;
                int gm = bm0 + r, gk = ktn + c;
                areg[i] = (gm < M && gk < K) ? A[(size_t)gm * K + gk] : 0.f;
            }
#pragma unroll
            for (int i = 0; i < 4; i++) {
                int e = tid + i * 256, r = e >> 6, c = e & 63;
                int gk = ktn + r, gn = bn0 + c;
                breg[i] = (gk < K && gn < N) ? B[(size_t)gk * N + gn] : 0.f;
            }
        }
        // compute current tile: two k8 sub-steps
#pragma unroll
        for (int kk = 0; kk < BK; kk += 8) {
            unsigned ah[2][4], al[2][4], bh[4][2], bl[4][2];
#pragma unroll
            for (int mt = 0; mt < 2; mt++) {
                int row = wm + mt * 16;
                split_tf32(As[row + g    ][kk + tig    ], ah[mt][0], al[mt][0]);
                split_tf32(As[row + g + 8][kk + tig    ], ah[mt][1], al[mt][1]);
                split_tf32(As[row + g    ][kk + tig + 4], ah[mt][2], al[mt][2]);
                split_tf32(As[row + g + 8][kk + tig + 4], ah[mt][3], al[mt][3]);
            }
#pragma unroll
            for (int nt = 0; nt < 4; nt++) {
                int col = wn + nt * 8 + g;
                split_tf32(Bs[kk + tig    ][col], bh[nt][0], bl[nt][0]);
                split_tf32(Bs[kk + tig + 4][col], bh[nt][1], bl[nt][1]);
            }
#pragma unroll
            for (int mt = 0; mt < 2; mt++)
#pragma unroll
                for (int nt = 0; nt < 4; nt++) {
                    mma_tf32(acc[mt][nt], ah[mt], bl[nt]);
                    mma_tf32(acc[mt][nt], al[mt], bh[nt]);
                    mma_tf32(acc[mt][nt], ah[mt], bh[nt]);
                }
        }
        __syncthreads();
        if (step + 1 < nk) {
#pragma unroll
            for (int i = 0; i < 8; i++) { int e = tid + i * 256; As[e >> 4][e & 15] = areg[i]; }
#pragma unroll
            for (int i = 0; i < 4; i++) { int e = tid + i * 256; Bs[e >> 6][e & 63] = breg[i]; }
            __syncthreads();
        }
    }

    // epilogue
#pragma unroll
    for (int mt = 0; mt < 2; mt++) {
        int gm0 = bm0 + wm + mt * 16 + g;
#pragma unroll
        for (int nt = 0; nt < 4; nt++) {
            int gn = bn0 + wn + nt * 8 + tig * 2;
            float* cc = acc[mt][nt];
#pragma unroll
            for (int half = 0; half < 2; half++) {
                int gm = gm0 + half * 8;
                if (gm >= M) continue;
#pragma unroll
                for (int q = 0; q < 2; q++) {
                    int gnn = gn + q;
                    if (gnn >= N) continue;
                    float v = cc[half * 2 + q] * alpha;
                    if (bias) v += bias[gnn];
                    if (do_relu) v = fmaxf(v, 0.f);
                    C[(size_t)gm * N + gnn] = v;
                }
            }
        }
    }
}

// ---------------- batchnorm ---------------------------------------------------
__global__ void bn_stats_kernel(const float* __restrict__ h, float* __restrict__ stats,
                                int n) {
    int t = threadIdx.x;
    if (t >= EMB) return;
    float s = 0.f, sq = 0.f;
    for (int r = blockIdx.x; r < n; r += gridDim.x) {
        float v = h[(size_t)r * EMB + t];
        s += v; sq += v * v;
    }
    atomicAdd(&stats[t], s);
    atomicAdd(&stats[EMB + t], sq);
}

__global__ void bn_apply_kernel(float* __restrict__ h, const float* __restrict__ stats,
                                const float* __restrict__ gamma,
                                const float* __restrict__ beta,
                                int n, int do_relu) {
    int idx = blockIdx.x * blockDim.x + threadIdx.x;
    if (idx >= n * EMB) return;
    int c = idx % EMB;
    float invn = 1.f / (float)n;
    float mean = stats[c] * invn;
    float var  = stats[EMB + c] * invn - mean * mean;
    float inv  = rsqrtf(var + BN_EPS);
    float v = (h[idx] - mean) * inv * gamma[c] + beta[c];
    if (do_relu) v = fmaxf(v, 0.f);
    h[idx] = v;
}

// ---------------- pooling + normalize ----------------------------------------
__global__ void pool_kernel(const float* __restrict__ p, const int* __restrict__ batch,
                            float* __restrict__ feat, float* __restrict__ cnt, int n) {
    int gw   = (blockIdx.x * blockDim.x + threadIdx.x) >> 5;
    int lane = threadIdx.x & 31;
    if (gw >= n) return;
    int b = batch[gw];
    if (lane == 0) atomicAdd(&cnt[b], 1.f);
    const float* pr = p + (size_t)gw * EMB;
    float* fr = feat + (size_t)b * EMB;
    for (int c = lane; c < EMB; c += 32) atomicAdd(fr + c, pr[c]);
}

__global__ void norm_feat_kernel(float* __restrict__ feat, const float* __restrict__ cnt) {
    __shared__ float red[16];
    int g = blockIdx.x, t = threadIdx.x;
    float c = fmaxf(cnt[g], 1.f);
    float v = 0.f;
    if (t < EMB) v = feat[(size_t)g * EMB + t] / c;
    float sq = v * v;
#pragma unroll
    for (int o = 16; o; o >>= 1) sq += __shfl_xor_sync(0xffffffffu, sq, o);
    if ((t & 31) == 0) red[t >> 5] = sq;
    __syncthreads();
    if (t < 32) {
        float s = (t < (int)(blockDim.x >> 5)) ? red[t] : 0.f;
#pragma unroll
        for (int o = 16; o; o >>= 1) s += __shfl_xor_sync(0xffffffffu, s, o);
        if (t == 0) red[0] = s;
    }
    __syncthreads();
    float nrm = fmaxf(sqrtf(red[0]), 1e-12f);
    if (t < EMB) feat[(size_t)g * EMB + t] = v / nrm;
}

// transpose [NG,EMB] -> [EMB,NG]
__global__ void transpose_kernel(const float* __restrict__ f, float* __restrict__ ft) {
    int idx = blockIdx.x * blockDim.x + threadIdx.x;
    if (idx >= NG * EMB) return;
    int g = idx / EMB, c = idx - g * EMB;
    ft[(size_t)c * NG + g] = f[idx];
}

// ---------------- driver ------------------------------------------------------
extern "C" void kernel_launch(void* const* d_in, const int* in_sizes, int n_in,
                              void* d_out, int out_size) {
    const int* x[2]  = {(const int*)d_in[0], (const int*)d_in[4]};
    const int* ei[2] = {(const int*)d_in[1], (const int*)d_in[5]};
    const int* ea[2] = {(const int*)d_in[2], (const int*)d_in[6]};
    const int* bt[2] = {(const int*)d_in[3], (const int*)d_in[7]};
    const float* ae1 = (const float*)d_in[8];
    const float* ae2 = (const float*)d_in[9];
    const float* ee1 = (const float*)d_in[10];
    const float* ee2 = (const float*)d_in[11];
    const float* w1  = (const float*)d_in[12];
    const float* b1  = (const float*)d_in[13];
    const float* w2  = (const float*)d_in[14];
    const float* b2  = (const float*)d_in[15];
    const float* gam = (const float*)d_in[16];
    const float* bet = (const float*)d_in[17];
    const float* pw  = (const float*)d_in[18];
    const float* pb  = (const float*)d_in[19];

    int Nn[2] = {in_sizes[0] / 2, in_sizes[4] / 2};
    int Ee[2] = {in_sizes[1] / 2, in_sizes[5] / 2};

    float *h, *agg, *h2, *stats, *feat0, *feat1, *cnt, *f1t, *et;
    int *off, *cur, *bsum, *csr;
    cudaGetSymbolAddress((void**)&h,     g_h);
    cudaGetSymbolAddress((void**)&agg,   g_agg);
    cudaGetSymbolAddress((void**)&h2,    g_h2);
    cudaGetSymbolAddress((void**)&stats, g_stats);
    cudaGetSymbolAddress((void**)&feat0, g_feat0);
    cudaGetSymbolAddress((void**)&feat1, g_feat1);
    cudaGetSymbolAddress((void**)&cnt,   g_cnt);
    cudaGetSymbolAddress((void**)&f1t,   g_f1t);
    cudaGetSymbolAddress((void**)&et,    g_etab);
    cudaGetSymbolAddress((void**)&off,   g_off);
    cudaGetSymbolAddress((void**)&cur,   g_cur);
    cudaGetSymbolAddress((void**)&bsum,  g_bsum);
    cudaGetSymbolAddress((void**)&csr,   g_csr);

    etab_kernel<<<(NL * 18 * EMB + 255) / 256, 256>>>(ee1, ee2, et);

    for (int br = 0; br < 2; br++) {
        int n = Nn[br], e = Ee[br];
        float* feat_b = br ? feat1 : feat0;
        int elemBlocks = (n * EMB + 255) / 256;
        int G = (n + 1023) / 1024;

        // build CSR (dst-sorted adjacency), reused for all 5 layers
        zero_i<<<(n + 255) / 256, 256>>>(cur, n);
        count_deg_kernel<<<(e + 255) / 256, 256>>>(ei[br], cur, e);
        scan1_kernel<<<G, 1024>>>(cur, off, bsum, n);
        scan2_kernel<<<1, 32>>>(bsum, G);
        scan3_kernel<<<G, 1024>>>(off, bsum, n);
        copy_cur_kernel<<<(n + 255) / 256, 256>>>(off, cur, n);
        fill_csr_kernel<<<(e + 255) / 256, 256>>>(ei[br], ea[br], cur, csr, e);

        init_h_kernel<<<elemBlocks, 256>>>(x[br], ae1, ae2, h, n);

        for (int l = 0; l < NL; l++) {
            const float* etl = et + (size_t)l * 18 * EMB;

            gather_kernel<<<(n + 7) / 8, 256>>>(h, off, csr, etl, agg, n);

            // h2 = relu(agg @ W1 + b1)   [n,300]x[300,600]
            gemm_tf32_kernel<<<dim3((EMB2 + BNT - 1) / BNT, (n + BM - 1) / BM), 256>>>(
                agg, w1 + (size_t)l * EMB * EMB2, b1 + (size_t)l * EMB2,
                h2, n, EMB2, EMB, 1.f, 1);
            // h = h2 @ W2 + b2          [n,600]x[600,300]
            gemm_tf32_kernel<<<dim3((EMB + BNT - 1) / BNT, (n + BM - 1) / BM), 256>>>(
                h2, w2 + (size_t)l * EMB2 * EMB, b2 + (size_t)l * EMB,
                h, n, EMB, EMB2, 1.f, 0);

            zero_f<<<(2 * EMB + 255) / 256, 256>>>(stats, 2 * EMB);
            bn_stats_kernel<<<512, 320>>>(h, stats, n);
            bn_apply_kernel<<<elemBlocks, 256>>>(h, stats, gam + (size_t)l * EMB,
                                                 bet + (size_t)l * EMB, n, l != NL - 1);
        }

        // projector: agg = h @ proj_w + proj_b
        gemm_tf32_kernel<<<dim3((EMB + BNT - 1) / BNT, (n + BM - 1) / BM), 256>>>(
            h, pw, pb, agg, n, EMB, EMB, 1.f, 0);

        zero_f<<<(NG * EMB + 255) / 256, 256>>>(feat_b, NG * EMB);
        zero_f<<<(NG + 255) / 256, 256>>>(cnt, NG);
        pool_kernel<<<(n * 32 + 255) / 256, 256>>>(agg, bt[br], feat_b, cnt, n);
        norm_feat_kernel<<<NG, 320>>>(feat_b, cnt);
    }

    // logits = f0 @ f1^T / TEMP
    transpose_kernel<<<(NG * EMB + 255) / 256, 256>>>(feat1, f1t);
    gemm_tf32_kernel<<<dim3(NG / BNT, NG / BM), 256>>>(
        feat0, f1t, nullptr, (float*)d_out, NG, NG, EMB, INV_TEMP, 0);
}

// round 4
// speedup vs baseline: 2.0076x; 1.3293x over previous
#include <cuda_runtime.h>
#include <cuda_bf16.h>
#include <stdint.h>
#include <math.h>

#define EMB   300
#define EMB2  600
#define NG    4096
#define NL    5
#define MAXN  100000
#define MAXE  400000
#define BN_EPS 1e-5f
#define INV_TEMP 25.0f

// ---------------- scratch (device globals; no allocation allowed) -----------
__device__ float g_h   [(size_t)MAXN * EMB];
__device__ float g_agg [(size_t)MAXN * EMB];
__device__ float g_h2  [(size_t)MAXN * EMB2];
__device__ float g_stats[2 * EMB];
__device__ float g_feat0[(size_t)NG * EMB];
__device__ float g_feat1[(size_t)NG * EMB];
__device__ float g_cnt [NG];
__device__ float g_f1t [(size_t)EMB * NG];
__device__ float g_etab[(size_t)NL * 18 * EMB];   // e1[a0]+e2[a1] per layer
__device__ int   g_off [MAXN + 1];
__device__ int   g_cur [MAXN];
__device__ int   g_bsum[256];
__device__ int   g_csr [MAXE];

// ---------------- small utility kernels -------------------------------------
__global__ void zero_f(float* p, int n) {
    int i = blockIdx.x * blockDim.x + threadIdx.x;
    if (i < n) p[i] = 0.f;
}
__global__ void zero_i(int* p, int n) {
    int i = blockIdx.x * blockDim.x + threadIdx.x;
    if (i < n) p[i] = 0;
}

__global__ void init_h_kernel(const int* __restrict__ x,
                              const float* __restrict__ ae1,
                              const float* __restrict__ ae2,
                              float* __restrict__ h, int n) {
    int idx = blockIdx.x * blockDim.x + threadIdx.x;
    if (idx >= n * EMB) return;
    int i = idx / EMB, c = idx - i * EMB;
    h[idx] = ae1[x[2 * i] * EMB + c] + ae2[x[2 * i + 1] * EMB + c];
}

__global__ void etab_kernel(const float* __restrict__ ee1,
                            const float* __restrict__ ee2,
                            float* __restrict__ et) {
    int idx = blockIdx.x * blockDim.x + threadIdx.x;
    if (idx >= NL * 18 * EMB) return;
    int l = idx / (18 * EMB);
    int r = idx - l * 18 * EMB;
    int combo = r / EMB, c = r - combo * EMB;
    int a0 = combo / 3, a1 = combo - a0 * 3;
    et[idx] = ee1[(size_t)l * 6 * EMB + a0 * EMB + c] +
              ee2[(size_t)l * 3 * EMB + a1 * EMB + c];
}

// ---------------- CSR build ---------------------------------------------------
__global__ void count_deg_kernel(const int* __restrict__ ei, int* __restrict__ deg,
                                 int E) {
    int e = blockIdx.x * blockDim.x + threadIdx.x;
    if (e < E) atomicAdd(&deg[ei[E + e]], 1);
}

__global__ void scan1_kernel(const int* __restrict__ deg, int* __restrict__ off,
                             int* __restrict__ bsum, int n) {
    __shared__ int s[1024];
    int t = threadIdx.x;
    int i = blockIdx.x * 1024 + t;
    int v = (i < n) ? deg[i] : 0;
    s[t] = v;
    __syncthreads();
    for (int o = 1; o < 1024; o <<= 1) {
        int add = (t >= o) ? s[t - o] : 0;
        __syncthreads();
        s[t] += add;
        __syncthreads();
    }
    if (i < n) off[i + 1] = s[t];
    if (t == 1023) bsum[blockIdx.x] = s[1023];
}

__global__ void scan2_kernel(int* bsum, int G) {
    if (threadIdx.x == 0 && blockIdx.x == 0) {
        int run = 0;
        for (int b = 0; b < G; b++) { int v = bsum[b]; bsum[b] = run; run += v; }
    }
}

__global__ void scan3_kernel(int* __restrict__ off, const int* __restrict__ bsum,
                             int n) {
    int i = blockIdx.x * 1024 + threadIdx.x;
    if (i < n) off[i + 1] += bsum[blockIdx.x];
    if (i == 0) off[0] = 0;
}

__global__ void copy_cur_kernel(const int* __restrict__ off, int* __restrict__ cur,
                                int n) {
    int i = blockIdx.x * blockDim.x + threadIdx.x;
    if (i < n) cur[i] = off[i];
}

__global__ void fill_csr_kernel(const int* __restrict__ ei, const int* __restrict__ ea,
                                int* __restrict__ cur, int* __restrict__ csr, int E) {
    int e = blockIdx.x * blockDim.x + threadIdx.x;
    if (e >= E) return;
    int d = ei[E + e];
    int p = atomicAdd(&cur[d], 1);
    int a = ea[2 * e] * 3 + ea[2 * e + 1];
    csr[p] = ei[e] | (a << 20);
}

// ---------------- message aggregation (gather, no atomics) -------------------
__global__ void gather_kernel(const float* __restrict__ h,
                              const int* __restrict__ off,
                              const int* __restrict__ csr,
                              const float* __restrict__ et,
                              float* __restrict__ agg, int n) {
    int w    = (blockIdx.x * blockDim.x + threadIdx.x) >> 5;
    int lane = threadIdx.x & 31;
    if (w >= n) return;
    int o0 = off[w], o1 = off[w + 1];
    const float* hd    = h + (size_t)w * EMB;
    const float* selft = et + 12 * EMB;   // combo (4,0) = self-loop
    float r[10];
#pragma unroll
    for (int j = 0; j < 10; j++) {
        int c = lane + 32 * j;
        r[j] = (c < EMB) ? hd[c] + selft[c] : 0.f;
    }
    for (int o = o0; o < o1; o++) {
        int pk = csr[o];
        const float* hs = h  + (size_t)(pk & 0xFFFFF) * EMB;
        const float* tt = et + (size_t)(pk >> 20) * EMB;
#pragma unroll
        for (int j = 0; j < 10; j++) {
            int c = lane + 32 * j;
            if (c < EMB) r[j] += hs[c] + tt[c];
        }
    }
    float* ad = agg + (size_t)w * EMB;
#pragma unroll
    for (int j = 0; j < 10; j++) {
        int c = lane + 32 * j;
        if (c < EMB) ad[c] = r[j];
    }
}

// ---------------- 3xBF16 tensor-core GEMM ------------------------------------
// C[M,N] = act(alpha * A[M,K] @ B[K,N] + bias). A,B row-major fp32.
// Split each operand into bf16 hi + lo at smem-staging time; inner loop does
// mma.m16n8k16.bf16 with terms ah*bh + ah*bl + al*bh (al*bl dropped, ~2^-18).
// Block 256 thr (8 warps, 4x2), tile 128x64, BK=32, warp tile 32x32.
#define BM  128
#define BNT 64
#define BK  32
#define STR 20   // smem row stride in uint32 (16 data + 4 pad): 20g+tig is a
                 // perfect mod-32 bank permutation for g<8, tig<4

__device__ __forceinline__ uint32_t pack_bf(float a, float b) {
    __nv_bfloat162 t = __floats2bfloat162_rn(a, b);   // .x = a (low), .y = b (high)
    uint32_t r;
    memcpy(&r, &t, 4);
    return r;
}
__device__ __forceinline__ float bf_hi(float v) {
    return __bfloat162float(__float2bfloat16_rn(v));
}
__device__ __forceinline__ void mma_bf16(float* c, const uint32_t* a, const uint32_t* b) {
    asm volatile(
        "mma.sync.aligned.m16n8k16.row.col.f32.bf16.bf16.f32 "
        "{%0,%1,%2,%3},{%4,%5,%6,%7},{%8,%9},{%0,%1,%2,%3};"
        : "+f"(c[0]), "+f"(c[1]), "+f"(c[2]), "+f"(c[3])
        : "r"(a[0]), "r"(a[1]), "r"(a[2]), "r"(a[3]), "r"(b[0]), "r"(b[1]));
}

__global__ __launch_bounds__(256)
void gemm_bf16_kernel(const float* __restrict__ A, const float* __restrict__ B,
                      const float* __restrict__ bias, float* __restrict__ C,
                      int M, int N, int K, float alpha, int do_relu) {
    __shared__ uint32_t As_hi[BM * STR];
    __shared__ uint32_t As_lo[BM * STR];
    __shared__ uint32_t Bs_hi[BNT * STR];
    __shared__ uint32_t Bs_lo[BNT * STR];

    int tid  = threadIdx.x;
    int wid  = tid >> 5;
    int lane = tid & 31;
    int g    = lane >> 2;
    int tig  = lane & 3;
    int wm   = (wid & 3) * 32;
    int wn   = (wid >> 2) * 32;
    int bm0  = blockIdx.y * BM;
    int bn0  = blockIdx.x * BNT;

    float acc[2][4][4];
#pragma unroll
    for (int mt = 0; mt < 2; mt++)
#pragma unroll
        for (int nt = 0; nt < 4; nt++)
#pragma unroll
            for (int q = 0; q < 4; q++) acc[mt][nt][q] = 0.f;

    int nk = (K + BK - 1) / BK;

    // A staging indices: thread -> (row, 16-col half)
    int ar = tid >> 1;
    int ac = (tid & 1) * 16;
    // B staging: thread -> (col, base k-pair)
    int bcol = tid & 63;
    int bkp  = tid >> 6;

    for (int step = 0; step < nk; step++) {
        int kt = step * BK;

        // ---- stage A tile (128 x 32 fp32 -> hi/lo bf16x2) ----
        {
            int gm = bm0 + ar;
            const float* Ar = A + (size_t)gm * K;
            bool rok = gm < M;
#pragma unroll
            for (int i = 0; i < 4; i++) {
                int k0 = kt + ac + i * 4;
                float4 v;
                if (rok && k0 + 4 <= K) {
                    v = *(const float4*)(Ar + k0);
                } else {
                    v.x = (rok && k0     < K) ? Ar[k0]     : 0.f;
                    v.y = (rok && k0 + 1 < K) ? Ar[k0 + 1] : 0.f;
                    v.z = (rok && k0 + 2 < K) ? Ar[k0 + 2] : 0.f;
                    v.w = (rok && k0 + 3 < K) ? Ar[k0 + 3] : 0.f;
                }
                float hx = bf_hi(v.x), hy = bf_hi(v.y), hz = bf_hi(v.z), hw = bf_hi(v.w);
                int kk = (ac >> 1) + i * 2;
                As_hi[ar * STR + kk]     = pack_bf(hx, hy);
                As_hi[ar * STR + kk + 1] = pack_bf(hz, hw);
                As_lo[ar * STR + kk]     = pack_bf(v.x - hx, v.y - hy);
                As_lo[ar * STR + kk + 1] = pack_bf(v.z - hz, v.w - hw);
            }
        }
        // ---- stage B tile (32 x 64 fp32 -> hi/lo bf16x2, k-pair packed) ----
        {
            int gn = bn0 + bcol;
            bool cok = gn < N;
#pragma unroll
            for (int j = 0; j < 4; j++) {
                int kp = bkp + j * 4;          // k-pair index 0..15
                int k0 = kt + kp * 2;
                float f0 = (cok && k0     < K) ? B[(size_t)k0 * N + gn]       : 0.f;
                float f1 = (cok && k0 + 1 < K) ? B[(size_t)(k0 + 1) * N + gn] : 0.f;
                float h0 = bf_hi(f0), h1 = bf_hi(f1);
                Bs_hi[bcol * STR + kp] = pack_bf(h0, h1);
                Bs_lo[bcol * STR + kp] = pack_bf(f0 - h0, f1 - h1);
            }
        }
        __syncthreads();

        // ---- compute: two k16 substeps ----
#pragma unroll
        for (int s = 0; s < 2; s++) {
            int kk = s * 8 + tig;
            uint32_t ah[2][4], al[2][4], bh[4][2], bl[4][2];
#pragma unroll
            for (int mt = 0; mt < 2; mt++) {
                int r0 = (wm + mt * 16 + g) * STR;
                int r1 = r0 + 8 * STR;
                ah[mt][0] = As_hi[r0 + kk];
                ah[mt][1] = As_hi[r1 + kk];
                ah[mt][2] = As_hi[r0 + kk + 4];
                ah[mt][3] = As_hi[r1 + kk + 4];
                al[mt][0] = As_lo[r0 + kk];
                al[mt][1] = As_lo[r1 + kk];
                al[mt][2] = As_lo[r0 + kk + 4];
                al[mt][3] = As_lo[r1 + kk + 4];
            }
#pragma unroll
            for (int nt = 0; nt < 4; nt++) {
                int c0 = (wn + nt * 8 + g) * STR;
                bh[nt][0] = Bs_hi[c0 + kk];
                bh[nt][1] = Bs_hi[c0 + kk + 4];
                bl[nt][0] = Bs_lo[c0 + kk];
                bl[nt][1] = Bs_lo[c0 + kk + 4];
            }
#pragma unroll
            for (int mt = 0; mt < 2; mt++)
#pragma unroll
                for (int nt = 0; nt < 4; nt++) {
                    mma_bf16(acc[mt][nt], ah[mt], bl[nt]);
                    mma_bf16(acc[mt][nt], al[mt], bh[nt]);
                    mma_bf16(acc[mt][nt], ah[mt], bh[nt]);
                }
        }
        __syncthreads();
    }

    // ---- epilogue ----
#pragma unroll
    for (int mt = 0; mt < 2; mt++) {
        int gm0 = bm0 + wm + mt * 16 + g;
#pragma unroll
        for (int nt = 0; nt < 4; nt++) {
            int gn = bn0 + wn + nt * 8 + tig * 2;
            float* cc = acc[mt][nt];
#pragma unroll
            for (int half = 0; half < 2; half++) {
                int gm = gm0 + half * 8;
                if (gm >= M) continue;
#pragma unroll
                for (int q = 0; q < 2; q++) {
                    int gnn = gn + q;
                    if (gnn >= N) continue;
                    float v = cc[half * 2 + q] * alpha;
                    if (bias) v += bias[gnn];
                    if (do_relu) v = fmaxf(v, 0.f);
                    C[(size_t)gm * N + gnn] = v;
                }
            }
        }
    }
}

// ---------------- batchnorm ---------------------------------------------------
__global__ void bn_stats_kernel(const float* __restrict__ h, float* __restrict__ stats,
                                int n) {
    int t = threadIdx.x;
    if (t >= EMB) return;
    float s = 0.f, sq = 0.f;
    for (int r = blockIdx.x; r < n; r += gridDim.x) {
        float v = h[(size_t)r * EMB + t];
        s += v; sq += v * v;
    }
    atomicAdd(&stats[t], s);
    atomicAdd(&stats[EMB + t], sq);
}

__global__ void bn_apply_kernel(float* __restrict__ h, const float* __restrict__ stats,
                                const float* __restrict__ gamma,
                                const float* __restrict__ beta,
                                int n, int do_relu) {
    int idx = blockIdx.x * blockDim.x + threadIdx.x;
    if (idx >= n * EMB) return;
    int c = idx % EMB;
    float invn = 1.f / (float)n;
    float mean = stats[c] * invn;
    float var  = stats[EMB + c] * invn - mean * mean;
    float inv  = rsqrtf(var + BN_EPS);
    float v = (h[idx] - mean) * inv * gamma[c] + beta[c];
    if (do_relu) v = fmaxf(v, 0.f);
    h[idx] = v;
}

// ---------------- pooling + normalize ----------------------------------------
__global__ void pool_kernel(const float* __restrict__ p, const int* __restrict__ batch,
                            float* __restrict__ feat, float* __restrict__ cnt, int n) {
    int gw   = (blockIdx.x * blockDim.x + threadIdx.x) >> 5;
    int lane = threadIdx.x & 31;
    if (gw >= n) return;
    int b = batch[gw];
    if (lane == 0) atomicAdd(&cnt[b], 1.f);
    const float* pr = p + (size_t)gw * EMB;
    float* fr = feat + (size_t)b * EMB;
    for (int c = lane; c < EMB; c += 32) atomicAdd(fr + c, pr[c]);
}

__global__ void norm_feat_kernel(float* __restrict__ feat, const float* __restrict__ cnt) {
    __shared__ float red[16];
    int g = blockIdx.x, t = threadIdx.x;
    float c = fmaxf(cnt[g], 1.f);
    float v = 0.f;
    if (t < EMB) v = feat[(size_t)g * EMB + t] / c;
    float sq = v * v;
#pragma unroll
    for (int o = 16; o; o >>= 1) sq += __shfl_xor_sync(0xffffffffu, sq, o);
    if ((t & 31) == 0) red[t >> 5] = sq;
    __syncthreads();
    if (t < 32) {
        float s = (t < (int)(blockDim.x >> 5)) ? red[t] : 0.f;
#pragma unroll
        for (int o = 16; o; o >>= 1) s += __shfl_xor_sync(0xffffffffu, s, o);
        if (t == 0) red[0] = s;
    }
    __syncthreads();
    float nrm = fmaxf(sqrtf(red[0]), 1e-12f);
    if (t < EMB) feat[(size_t)g * EMB + t] = v / nrm;
}

__global__ void transpose_kernel(const float* __restrict__ f, float* __restrict__ ft) {
    int idx = blockIdx.x * blockDim.x + threadIdx.x;
    if (idx >= NG * EMB) return;
    int g = idx / EMB, c = idx - g * EMB;
    ft[(size_t)c * NG + g] = f[idx];
}

// ---------------- driver ------------------------------------------------------
extern "C" void kernel_launch(void* const* d_in, const int* in_sizes, int n_in,
                              void* d_out, int out_size) {
    const int* x[2]  = {(const int*)d_in[0], (const int*)d_in[4]};
    const int* ei[2] = {(const int*)d_in[1], (const int*)d_in[5]};
    const int* ea[2] = {(const int*)d_in[2], (const int*)d_in[6]};
    const int* bt[2] = {(const int*)d_in[3], (const int*)d_in[7]};
    const float* ae1 = (const float*)d_in[8];
    const float* ae2 = (const float*)d_in[9];
    const float* ee1 = (const float*)d_in[10];
    const float* ee2 = (const float*)d_in[11];
    const float* w1  = (const float*)d_in[12];
    const float* b1  = (const float*)d_in[13];
    const float* w2  = (const float*)d_in[14];
    const float* b2  = (const float*)d_in[15];
    const float* gam = (const float*)d_in[16];
    const float* bet = (const float*)d_in[17];
    const float* pw  = (const float*)d_in[18];
    const float* pb  = (const float*)d_in[19];

    int Nn[2] = {in_sizes[0] / 2, in_sizes[4] / 2};
    int Ee[2] = {in_sizes[1] / 2, in_sizes[5] / 2};

    float *h, *agg, *h2, *stats, *feat0, *feat1, *cnt, *f1t, *et;
    int *off, *cur, *bsum, *csr;
    cudaGetSymbolAddress((void**)&h,     g_h);
    cudaGetSymbolAddress((void**)&agg,   g_agg);
    cudaGetSymbolAddress((void**)&h2,    g_h2);
    cudaGetSymbolAddress((void**)&stats, g_stats);
    cudaGetSymbolAddress((void**)&feat0, g_feat0);
    cudaGetSymbolAddress((void**)&feat1, g_feat1);
    cudaGetSymbolAddress((void**)&cnt,   g_cnt);
    cudaGetSymbolAddress((void**)&f1t,   g_f1t);
    cudaGetSymbolAddress((void**)&et,    g_etab);
    cudaGetSymbolAddress((void**)&off,   g_off);
    cudaGetSymbolAddress((void**)&cur,   g_cur);
    cudaGetSymbolAddress((void**)&bsum,  g_bsum);
    cudaGetSymbolAddress((void**)&csr,   g_csr);

    etab_kernel<<<(NL * 18 * EMB + 255) / 256, 256>>>(ee1, ee2, et);

    for (int br = 0; br < 2; br++) {
        int n = Nn[br], e = Ee[br];
        float* feat_b = br ? feat1 : feat0;
        int elemBlocks = (n * EMB + 255) / 256;
        int G = (n + 1023) / 1024;

        // build CSR (dst-sorted adjacency), reused for all 5 layers
        zero_i<<<(n + 255) / 256, 256>>>(cur, n);
        count_deg_kernel<<<(e + 255) / 256, 256>>>(ei[br], cur, e);
        scan1_kernel<<<G, 1024>>>(cur, off, bsum, n);
        scan2_kernel<<<1, 32>>>(bsum, G);
        scan3_kernel<<<G, 1024>>>(off, bsum, n);
        copy_cur_kernel<<<(n + 255) / 256, 256>>>(off, cur, n);
        fill_csr_kernel<<<(e + 255) / 256, 256>>>(ei[br], ea[br], cur, csr, e);

        init_h_kernel<<<elemBlocks, 256>>>(x[br], ae1, ae2, h, n);

        for (int l = 0; l < NL; l++) {
            const float* etl = et + (size_t)l * 18 * EMB;

            gather_kernel<<<(n + 7) / 8, 256>>>(h, off, csr, etl, agg, n);

            // h2 = relu(agg @ W1 + b1)   [n,300]x[300,600]
            gemm_bf16_kernel<<<dim3((EMB2 + BNT - 1) / BNT, (n + BM - 1) / BM), 256>>>(
                agg, w1 + (size_t)l * EMB * EMB2, b1 + (size_t)l * EMB2,
                h2, n, EMB2, EMB, 1.f, 1);
            // h = h2 @ W2 + b2          [n,600]x[600,300]
            gemm_bf16_kernel<<<dim3((EMB + BNT - 1) / BNT, (n + BM - 1) / BM), 256>>>(
                h2, w2 + (size_t)l * EMB2 * EMB, b2 + (size_t)l * EMB,
                h, n, EMB, EMB2, 1.f, 0);

            zero_f<<<(2 * EMB + 255) / 256, 256>>>(stats, 2 * EMB);
            bn_stats_kernel<<<512, 320>>>(h, stats, n);
            bn_apply_kernel<<<elemBlocks, 256>>>(h, stats, gam + (size_t)l * EMB,
                                                 bet + (size_t)l * EMB, n, l != NL - 1);
        }

        // projector
        gemm_bf16_kernel<<<dim3((EMB + BNT - 1) / BNT, (n + BM - 1) / BM), 256>>>(
            h, pw, pb, agg, n, EMB, EMB, 1.f, 0);

        zero_f<<<(NG * EMB + 255) / 256, 256>>>(feat_b, NG * EMB);
        zero_f<<<(NG + 255) / 256, 256>>>(cnt, NG);
        pool_kernel<<<(n * 32 + 255) / 256, 256>>>(agg, bt[br], feat_b, cnt, n);
        norm_feat_kernel<<<NG, 320>>>(feat_b, cnt);
    }

    // logits = f0 @ f1^T / TEMP
    transpose_kernel<<<(NG * EMB + 255) / 256, 256>>>(feat1, f1t);
    gemm_bf16_kernel<<<dim3(NG / BNT, NG / BM), 256>>>(
        feat0, f1t, nullptr, (float*)d_out, NG, NG, EMB, INV_TEMP, 0);
}